// round 5
// baseline (speedup 1.0000x reference)
#include <cuda_runtime.h>
#include <cuda_bf16.h>
#include <cstdint>

// Problem constants
#define BV 8
#define NV 4096
#define DV 256
#define HIDV 1024
#define LV 6
#define MV (BV*NV)          // 32768 rows

// ---------------------------------------------------------------------------
// Scratch (static __device__ — no allocation allowed)
// ---------------------------------------------------------------------------
__device__ __nv_bfloat16 g_H0[(size_t)MV*DV];      // 16 MB
__device__ __nv_bfloat16 g_H1[(size_t)MV*DV];      // 16 MB
__device__ __nv_bfloat16 g_hid[(size_t)MV*HIDV];   // 64 MB (compact rows)
__device__ __nv_bfloat16 g_msgs[(size_t)MV*DV];    // 16 MB (compact rows; L0: 4096 shared)
__device__ __nv_bfloat16 g_giC[(size_t)MV*768];    // 48 MB (compact rows: all 3 gates of gi)
__device__ __nv_bfloat16 g_rz[(size_t)MV*512];     // 32 MB
__device__ int   g_win[MV];        // target row -> winning source index (within batch) or -1
__device__ int   g_rows[MV];       // compact slot -> global source row
__device__ int   g_rowsN[MV];      // compact slot -> source row mod NV (for L0 shared msgs)
__device__ int   g_islot[MV];      // target row -> compact slot or -1
__device__ int   g_cnt;            // number of winner rows
__device__ __nv_bfloat16 g_W1[HIDV*DV];
__device__ __nv_bfloat16 g_W2[DV*HIDV];
__device__ __nv_bfloat16 g_Wih[3*DV*DV];
__device__ __nv_bfloat16 g_Whh[3*DV*DV];
__device__ float g_comb[BV*DV];

// ---------------------------------------------------------------------------
// Helpers
// ---------------------------------------------------------------------------
__device__ __forceinline__ float geluf(float x) {
    return 0.5f * x * (1.0f + erff(x * 0.7071067811865476f));
}
__device__ __forceinline__ float sigmf(float x) {
    return 1.0f / (1.0f + __expf(-x));
}
__device__ __forceinline__ void cpasync16(uint32_t dst, const void* src) {
    asm volatile("cp.async.cg.shared.global [%0], [%1], 16;\n" :: "r"(dst), "l"(src));
}
__device__ __forceinline__ void ldsm_x4(unsigned r[4], uint32_t addr) {
    asm volatile("ldmatrix.sync.aligned.m8n8.x4.shared.b16 {%0,%1,%2,%3}, [%4];\n"
                 : "=r"(r[0]), "=r"(r[1]), "=r"(r[2]), "=r"(r[3]) : "r"(addr));
}
__device__ __forceinline__ void mma_bf16(float c[4], const unsigned a[4], const unsigned b[2]) {
    asm volatile(
        "mma.sync.aligned.m16n8k16.row.col.f32.bf16.bf16.f32 "
        "{%0,%1,%2,%3}, {%4,%5,%6,%7}, {%8,%9}, {%0,%1,%2,%3};\n"
        : "+f"(c[0]), "+f"(c[1]), "+f"(c[2]), "+f"(c[3])
        : "r"(a[0]), "r"(a[1]), "r"(a[2]), "r"(a[3]), "r"(b[0]), "r"(b[1]));
}

// ---------------------------------------------------------------------------
// Prep kernels
// ---------------------------------------------------------------------------
__global__ void k_prep(const float* __restrict__ W1, const float* __restrict__ W2,
                       const float* __restrict__ Wih, const float* __restrict__ Whh) {
    int i = blockIdx.x * 256 + threadIdx.x;           // grid covers HIDV*DV = 262144
    if (i < HIDV*DV) { g_W1[i] = __float2bfloat16_rn(W1[i]); g_W2[i] = __float2bfloat16_rn(W2[i]); }
    if (i < 3*DV*DV) { g_Wih[i] = __float2bfloat16_rn(Wih[i]); g_Whh[i] = __float2bfloat16_rn(Whh[i]); }
}

__global__ void k_h0(const float* __restrict__ emb) {
    int idx = blockIdx.x * 256 + threadIdx.x;         // MV*DV = 8388608
    g_H0[idx] = __float2bfloat16_rn(emb[idx & (NV*DV - 1)]);
}

__global__ void k_win_init() {
    int i = blockIdx.x * 256 + threadIdx.x;
    g_win[i] = -1;
    g_islot[i] = -1;
    g_rows[i] = 0;
    g_rowsN[i] = 0;
    if (i == 0) g_cnt = 0;
}
__global__ void k_win_fill(const int* __restrict__ p) {
    int i = blockIdx.x * 256 + threadIdx.x;           // MV
    int b = i >> 12, t = i & 4095;
    atomicMax(&g_win[(b << 12) + p[i]], t);
}
// Build compact winner list. Winners are unique per target; slot order is
// replay-dependent but output-invariant (rows independent; indexed via islot).
__global__ void k_compact() {
    int t = blockIdx.x * 256 + threadIdx.x;           // MV target rows
    int w = g_win[t];
    if (w >= 0) {
        int slot = atomicAdd(&g_cnt, 1);
        int src = ((t >> 12) << 12) | w;
        g_rows[slot]  = src;
        g_rowsN[slot] = w;          // L0: msgs shared across batch
        g_islot[t]    = slot;
    }
}

// ---------------------------------------------------------------------------
// BF16 GEMM, 128x128 tile, KC=32, 3-stage cp.async pipeline, fused epilogues
//   MODE 0: C = bf16(gelu(A@W^T + biasA))                  (hid)
//   MODE 1: C = bf16(A@W^T + biasA)                        (msgs, giC)
//   MODE 2: rz = sigmoid(gh + bhh + gi)   gi via islot/giC (rz)
//   MODE 3: GRU n-gate + state update     gi via islot/giC (Hn)
// GATHER: A rows indirected through rowIdx. cntPtr: blocks past count exit.
// Smem rows padded to 40 bf16 (80 B stride) => conflict-free ldmatrix.
// ---------------------------------------------------------------------------
template<bool GATHER>
__device__ __forceinline__ void load_tile(const __nv_bfloat16* __restrict__ Asrc,
                                          const int* __restrict__ rowIdx,
                                          const __nv_bfloat16* __restrict__ Wsrc,
                                          int lda, int kcol, long rowB, int colB,
                                          uint32_t smBase, int asOff, int bsOff, int tid) {
    #pragma unroll
    for (int i = 0; i < 2; i++) {                  // 128 rows * 4 chunks / 256 thr
        int idx = i*256 + tid; int r = idx >> 2, ck = idx & 3;
        long ar = GATHER ? (long)rowIdx[rowB + r] : (rowB + r);
        cpasync16(smBase + (unsigned)((asOff + r*40 + ck*8) * 2),
                  Asrc + ar * (long)lda + kcol + ck*8);
    }
    #pragma unroll
    for (int i = 0; i < 2; i++) {
        int idx = i*256 + tid; int r = idx >> 2, ck = idx & 3;
        cpasync16(smBase + (unsigned)((bsOff + r*40 + ck*8) * 2),
                  Wsrc + (long)(colB + r) * lda + kcol + ck*8);
    }
    asm volatile("cp.async.commit_group;\n" ::);
}

__device__ __forceinline__ void compute_tile(uint32_t aB, uint32_t bB, int lane,
                                             int wr0, int wc0, float acc[][4][4]) {
    #pragma unroll
    for (int kst = 0; kst < 2; kst++) {
        unsigned a[4][4], b[4][2];
        int arow = wr0 + (lane & 15);
        int acol = kst*16 + (lane >> 4) * 8;
        #pragma unroll
        for (int i = 0; i < 4; i++)
            ldsm_x4(a[i], aB + (unsigned)(((arow + i*16) * 40 + acol) * 2));
        #pragma unroll
        for (int jj = 0; jj < 2; jj++) {
            unsigned t[4];
            int brow = wc0 + jj*16 + (lane & 7) + ((lane >> 4) & 1) * 8;
            int bcol = kst*16 + ((lane >> 3) & 1) * 8;
            ldsm_x4(t, bB + (unsigned)((brow * 40 + bcol) * 2));
            b[jj*2][0]   = t[0]; b[jj*2][1]   = t[1];
            b[jj*2+1][0] = t[2]; b[jj*2+1][1] = t[3];
        }
        #pragma unroll
        for (int i = 0; i < 4; i++)
            #pragma unroll
            for (int j = 0; j < 4; j++)
                mma_bf16(acc[i][j], a[i], b[j]);
    }
}

template<int MODE, bool GATHER>
__global__ void __launch_bounds__(256)
k_gemm(const __nv_bfloat16* __restrict__ A, const __nv_bfloat16* __restrict__ W,
       const float* __restrict__ biasA, const float* __restrict__ biasB,
       __nv_bfloat16* __restrict__ C,
       const __nv_bfloat16* __restrict__ giC, const int* __restrict__ islot,
       const __nv_bfloat16* __restrict__ rzb, const __nv_bfloat16* __restrict__ Hin,
       const int* __restrict__ rowIdx, const int* __restrict__ cntPtr,
       int K, int Nout) {
    extern __shared__ __nv_bfloat16 sm[];
    const int tid = threadIdx.x, lane = tid & 31, warp = tid >> 5;
    const int wr0 = (warp >> 2) * 64, wc0 = (warp & 3) * 32;
    const long rowB = (long)blockIdx.x * 128;
    const int  colB = blockIdx.y * 128;

    if (cntPtr && rowB >= *cntPtr) return;   // uniform early exit (compact tail)

    uint32_t smBase = (uint32_t)__cvta_generic_to_shared(sm);
    const int asz = 128 * 40, bsz = 128 * 40;

    float acc[4][4][4];
    #pragma unroll
    for (int i = 0; i < 4; i++)
        #pragma unroll
        for (int j = 0; j < 4; j++)
            #pragma unroll
            for (int e = 0; e < 4; e++) acc[i][j][e] = 0.f;

    const int NK = K / 32;
    auto issue = [&](int k, int stage) {
        load_tile<GATHER>(A, rowIdx, W, K, k*32, rowB, colB, smBase,
                          stage*asz, 3*asz + stage*bsz, tid);
    };
    issue(0, 0);
    if (NK > 1) issue(1, 1);

    for (int kt = 0; kt < NK; kt++) {
        if (kt + 2 < NK) {
            issue(kt + 2, (kt + 2) % 3);
            asm volatile("cp.async.wait_group 2;\n" ::);
        } else if (kt + 1 < NK) {
            asm volatile("cp.async.wait_group 1;\n" ::);
        } else {
            asm volatile("cp.async.wait_group 0;\n" ::);
        }
        __syncthreads();
        const int st = kt % 3;
        compute_tile(smBase + (unsigned)((st * asz) * 2),
                     smBase + (unsigned)((3*asz + st * bsz) * 2),
                     lane, wr0, wc0, acc);
        __syncthreads();
    }

    const int laneR = lane >> 2, laneC = (lane & 3) * 2;
    #pragma unroll
    for (int i = 0; i < 4; i++) {
        #pragma unroll
        for (int e = 0; e < 2; e++) {
            long r = rowB + wr0 + i*16 + laneR + e*8;
            int is = (MODE >= 2) ? islot[r] : -1;
            const __nv_bfloat16* giRow = (MODE >= 2 && is >= 0)
                ? giC + (size_t)is * 768 + (MODE == 3 ? 512 : 0) : nullptr;
            #pragma unroll
            for (int j = 0; j < 4; j++) {
                int c = colB + wc0 + j*8 + laneC;
                float v0 = acc[i][j][e*2], v1 = acc[i][j][e*2+1];
                if (MODE == 0) {
                    __nv_bfloat162 o;
                    o.x = __float2bfloat16_rn(geluf(v0 + biasA[c]));
                    o.y = __float2bfloat16_rn(geluf(v1 + biasA[c+1]));
                    *reinterpret_cast<__nv_bfloat162*>(C + r*Nout + c) = o;
                } else if (MODE == 1) {
                    __nv_bfloat162 o;
                    o.x = __float2bfloat16_rn(v0 + biasA[c]);
                    o.y = __float2bfloat16_rn(v1 + biasA[c+1]);
                    *reinterpret_cast<__nv_bfloat162*>(C + r*Nout + c) = o;
                } else if (MODE == 2) {
                    float i0, i1;
                    if (is >= 0) {
                        float2 g = __bfloat1622float2(
                            *reinterpret_cast<const __nv_bfloat162*>(giRow + c));
                        i0 = g.x; i1 = g.y;
                    } else { i0 = biasB[c]; i1 = biasB[c+1]; }
                    __nv_bfloat162 o;
                    o.x = __float2bfloat16_rn(sigmf(v0 + biasA[c]   + i0));
                    o.y = __float2bfloat16_rn(sigmf(v1 + biasA[c+1] + i1));
                    *reinterpret_cast<__nv_bfloat162*>(C + r*Nout + c) = o;
                } else {
                    float i0, i1;
                    if (is >= 0) {
                        float2 g = __bfloat1622float2(
                            *reinterpret_cast<const __nv_bfloat162*>(giRow + c));
                        i0 = g.x; i1 = g.y;
                    } else { i0 = biasB[c]; i1 = biasB[c+1]; }
                    float h0 = v0 + biasA[c], h1 = v1 + biasA[c+1];
                    float2 rr = __bfloat1622float2(*reinterpret_cast<const __nv_bfloat162*>(rzb + r*512 + c));
                    float2 zz = __bfloat1622float2(*reinterpret_cast<const __nv_bfloat162*>(rzb + r*512 + 256 + c));
                    float2 hh = __bfloat1622float2(*reinterpret_cast<const __nv_bfloat162*>(Hin + r*256 + c));
                    float n0 = tanhf(fmaf(rr.x, h0, i0));
                    float n1 = tanhf(fmaf(rr.y, h1, i1));
                    __nv_bfloat162 o;
                    o.x = __float2bfloat16_rn(fmaf(zz.x, hh.x - n0, n0));   // (1-z)n + zH
                    o.y = __float2bfloat16_rn(fmaf(zz.y, hh.y - n1, n1));
                    *reinterpret_cast<__nv_bfloat162*>(C + r*256 + c) = o;
                }
            }
        }
    }
}

// ---------------------------------------------------------------------------
// Final head (tiny, fp32)
// ---------------------------------------------------------------------------
__global__ void k_combined(const __nv_bfloat16* __restrict__ Hfin, const int* __restrict__ s,
                           const int* __restrict__ kk, const float* __restrict__ emb,
                           const float* __restrict__ combW, const float* __restrict__ combB) {
    __shared__ float x[2*DV];
    int b = blockIdx.x, t = threadIdx.x;
    int srow = s[b], krow = kk[b];
    x[t]      = __bfloat162float(Hfin[((size_t)b*NV + srow)*DV + t]);
    x[DV + t] = emb[(size_t)krow*DV + t];
    __syncthreads();
    const float* w = combW + (size_t)t * (2*DV);
    float acc = combB[t];
    #pragma unroll 8
    for (int j = 0; j < 2*DV; j++) acc = fmaf(x[j], w[j], acc);
    g_comb[b*DV + t] = geluf(acc);
}

__global__ void k_logits(const float* __restrict__ headW, const float* __restrict__ headB,
                         float* __restrict__ out) {
    __shared__ float cb[BV*DV];
    for (int i = threadIdx.x; i < BV*DV; i += 256) cb[i] = g_comb[i];
    __syncthreads();
    int warp = threadIdx.x >> 5, lane = threadIdx.x & 31;
    int n = blockIdx.x * 8 + warp;                     // 512 blocks x 8 warps = 4096
    const float4* w4 = reinterpret_cast<const float4*>(headW + (size_t)n*DV);
    float acc[BV];
    #pragma unroll
    for (int b = 0; b < BV; b++) acc[b] = 0.f;
    #pragma unroll
    for (int c = lane; c < DV/4; c += 32) {
        float4 wv = w4[c];
        #pragma unroll
        for (int b = 0; b < BV; b++) {
            const float* cbb = &cb[b*DV + c*4];
            acc[b] += wv.x*cbb[0] + wv.y*cbb[1] + wv.z*cbb[2] + wv.w*cbb[3];
        }
    }
    #pragma unroll
    for (int off = 16; off; off >>= 1)
        #pragma unroll
        for (int b = 0; b < BV; b++)
            acc[b] += __shfl_down_sync(0xFFFFFFFFu, acc[b], off);
    if (lane == 0) {
        float hb = headB[n];
        #pragma unroll
        for (int b = 0; b < BV; b++) out[b*NV + n] = acc[b] + hb;
    }
}

// ---------------------------------------------------------------------------
// Host launcher
// ---------------------------------------------------------------------------
extern "C" void kernel_launch(void* const* d_in, const int* in_sizes, int n_in,
                              void* d_out, int out_size) {
    const int*   p     = (const int*)d_in[0];
    const int*   s     = (const int*)d_in[1];
    const int*   kk    = (const int*)d_in[2];
    const float* emb   = (const float*)d_in[3];
    const float* W1    = (const float*)d_in[4];
    const float* b1    = (const float*)d_in[5];
    const float* W2    = (const float*)d_in[6];
    const float* b2    = (const float*)d_in[7];
    const float* Wih   = (const float*)d_in[8];
    const float* Whh   = (const float*)d_in[9];
    const float* bih   = (const float*)d_in[10];
    const float* bhh   = (const float*)d_in[11];
    const float* combW = (const float*)d_in[12];
    const float* combB = (const float*)d_in[13];
    const float* headW = (const float*)d_in[14];
    const float* headB = (const float*)d_in[15];
    float* out = (float*)d_out;

    void *pH0, *pH1, *pHid, *pMsgs, *pGi, *pRz, *pW1, *pW2, *pWih, *pWhh;
    void *pRows, *pRowsN, *pIslot, *pCnt;
    cudaGetSymbolAddress(&pH0,  g_H0);
    cudaGetSymbolAddress(&pH1,  g_H1);
    cudaGetSymbolAddress(&pHid, g_hid);
    cudaGetSymbolAddress(&pMsgs,g_msgs);
    cudaGetSymbolAddress(&pGi,  g_giC);
    cudaGetSymbolAddress(&pRz,  g_rz);
    cudaGetSymbolAddress(&pW1,  g_W1);
    cudaGetSymbolAddress(&pW2,  g_W2);
    cudaGetSymbolAddress(&pWih, g_Wih);
    cudaGetSymbolAddress(&pWhh, g_Whh);
    cudaGetSymbolAddress(&pRows, g_rows);
    cudaGetSymbolAddress(&pRowsN,g_rowsN);
    cudaGetSymbolAddress(&pIslot,g_islot);
    cudaGetSymbolAddress(&pCnt,  g_cnt);

    const int SMB = 3*(128*40 + 128*40) * 2;       // 61440 B
    cudaFuncSetAttribute((const void*)k_gemm<0,false>, cudaFuncAttributeMaxDynamicSharedMemorySize, SMB);
    cudaFuncSetAttribute((const void*)k_gemm<0,true >, cudaFuncAttributeMaxDynamicSharedMemorySize, SMB);
    cudaFuncSetAttribute((const void*)k_gemm<1,false>, cudaFuncAttributeMaxDynamicSharedMemorySize, SMB);
    cudaFuncSetAttribute((const void*)k_gemm<1,true >, cudaFuncAttributeMaxDynamicSharedMemorySize, SMB);
    cudaFuncSetAttribute((const void*)k_gemm<2,false>, cudaFuncAttributeMaxDynamicSharedMemorySize, SMB);
    cudaFuncSetAttribute((const void*)k_gemm<3,false>, cudaFuncAttributeMaxDynamicSharedMemorySize, SMB);

    // Prep: round weights to bf16, build H0, winner indices + compaction
    k_prep<<<1024, 256>>>(W1, W2, Wih, Whh);
    k_h0<<<(MV*DV)/256, 256>>>(emb);
    k_win_init<<<MV/256, 256>>>();
    k_win_fill<<<MV/256, 256>>>(p);
    k_compact<<<MV/256, 256>>>();

    const __nv_bfloat16* bW1  = (const __nv_bfloat16*)pW1;
    const __nv_bfloat16* bW2  = (const __nv_bfloat16*)pW2;
    const __nv_bfloat16* bWih = (const __nv_bfloat16*)pWih;
    const __nv_bfloat16* bWhh = (const __nv_bfloat16*)pWhh;
    __nv_bfloat16* Hc = (__nv_bfloat16*)pH0;
    __nv_bfloat16* Hn = (__nv_bfloat16*)pH1;

    for (int l = 0; l < LV; l++) {
        if (l == 0) {
            // Layer 0: H identical across batch -> MLP on NV shared rows.
            k_gemm<0,false><<<dim3(NV/128, 8), 256, SMB>>>(
                Hc, bW1, b1, nullptr, (__nv_bfloat16*)pHid,
                nullptr, nullptr, nullptr, nullptr, nullptr, nullptr, 256, 1024);
            k_gemm<1,false><<<dim3(NV/128, 2), 256, SMB>>>(
                (__nv_bfloat16*)pHid, bW2, b2, nullptr, (__nv_bfloat16*)pMsgs,
                nullptr, nullptr, nullptr, nullptr, nullptr, nullptr, 1024, 256);
            // giC = msgs[rowsN] @ Wih^T + bih     (compact rows, all 3 gates)
            k_gemm<1,true><<<dim3(MV/128, 6), 256, SMB>>>(
                (__nv_bfloat16*)pMsgs, bWih, bih, nullptr, (__nv_bfloat16*)pGi,
                nullptr, nullptr, nullptr, nullptr,
                (const int*)pRowsN, (const int*)pCnt, 256, 768);
        } else {
            // Layers 1-5: MLP + giC only on winner rows (~63% of MV), compact.
            k_gemm<0,true><<<dim3(MV/128, 8), 256, SMB>>>(
                Hc, bW1, b1, nullptr, (__nv_bfloat16*)pHid,
                nullptr, nullptr, nullptr, nullptr,
                (const int*)pRows, (const int*)pCnt, 256, 1024);
            k_gemm<1,false><<<dim3(MV/128, 2), 256, SMB>>>(
                (__nv_bfloat16*)pHid, bW2, b2, nullptr, (__nv_bfloat16*)pMsgs,
                nullptr, nullptr, nullptr, nullptr,
                nullptr, (const int*)pCnt, 1024, 256);
            k_gemm<1,false><<<dim3(MV/128, 6), 256, SMB>>>(
                (__nv_bfloat16*)pMsgs, bWih, bih, nullptr, (__nv_bfloat16*)pGi,
                nullptr, nullptr, nullptr, nullptr,
                nullptr, (const int*)pCnt, 256, 768);
        }
        // rz = sigmoid(H@Whh_rz^T + bhh_rz + gi_rz)    N=512, K=256, dense
        k_gemm<2,false><<<dim3(MV/128, 4), 256, SMB>>>(
            Hc, bWhh, bhh, bih, (__nv_bfloat16*)pRz,
            (const __nv_bfloat16*)pGi, (const int*)pIslot, nullptr, nullptr,
            nullptr, nullptr, 256, 512);
        // n-gate + GRU update -> Hn                    N=256, K=256, dense
        k_gemm<3,false><<<dim3(MV/128, 2), 256, SMB>>>(
            Hc, bWhh + 512*DV, bhh + 512, bih + 512, Hn,
            (const __nv_bfloat16*)pGi, (const int*)pIslot,
            (const __nv_bfloat16*)pRz, Hc,
            nullptr, nullptr, 256, 256);
        __nv_bfloat16* t = Hc; Hc = Hn; Hn = t;
    }

    k_combined<<<BV, 256>>>(Hc, s, kk, emb, combW, combB);
    k_logits<<<NV/8, 256>>>(headW, headB, out);
}